// round 16
// baseline (speedup 1.0000x reference)
#include <cuda_runtime.h>
#include <cuda_bf16.h>
#include <cstdint>

constexpr int BB = 16, NN = 2048, DD = 64;
constexpr int TM = 128, TN = 128;
constexpr int THREADS = 256;          // 8 warps; warp w owns rows 16w..16w+15
constexpr int NT = NN / TN;           // 16 K-tiles
constexpr int KW = 36;                // K smem row stride in 4B words (72 bf16)

__device__ __forceinline__ uint32_t packbf(float x, float y) {
    __nv_bfloat162 h = __floats2bfloat162_rn(x, y);
    return *reinterpret_cast<uint32_t*>(&h);
}

__device__ __forceinline__ void mma16816(float* c, const uint32_t* a,
                                         uint32_t b0, uint32_t b1) {
    asm volatile(
        "mma.sync.aligned.m16n8k16.row.col.f32.bf16.bf16.f32 "
        "{%0,%1,%2,%3}, {%4,%5,%6,%7}, {%8,%9}, {%0,%1,%2,%3};"
        : "+f"(c[0]), "+f"(c[1]), "+f"(c[2]), "+f"(c[3])
        : "r"(a[0]), "r"(a[1]), "r"(a[2]), "r"(a[3]), "r"(b0), "r"(b1));
}

__device__ __forceinline__ void ldsm_x4(uint32_t& f0, uint32_t& f1,
                                        uint32_t& f2, uint32_t& f3, uint32_t addr) {
    asm volatile("ldmatrix.sync.aligned.m8n8.x4.shared.b16 {%0,%1,%2,%3}, [%4];"
                 : "=r"(f0), "=r"(f1), "=r"(f2), "=r"(f3) : "r"(addr));
}

constexpr unsigned NEGINF_BITS = 0xFF800000u;

// tile-local top-2 insert of packed (score|col); masked -> -inf falls through
__device__ __forceinline__ void ins2(float& A, float& B, float s, unsigned m, int col) {
    float pf = __int_as_float((__float_as_int(s) & 0xFFFFF800) | col);
    pf = m ? __int_as_float(NEGINF_BITS) : pf;
    float t = fminf(A, pf);
    A = fmaxf(A, pf);
    B = fmaxf(B, t);
}
// global top-4 insert of an already-packed value
__device__ __forceinline__ void ins4(float (&P)[4], float v) {
    float t1 = fminf(P[0], v); P[0] = fmaxf(P[0], v);
    float t2 = fminf(P[1], t1); P[1] = fmaxf(P[1], t1);
    float t3 = fminf(P[2], t2); P[2] = fmaxf(P[2], t2);
    P[3] = fmaxf(P[3], t3);
}

__global__ void __launch_bounds__(THREADS, 3)
attn_main_kernel(const float* __restrict__ q, const float* __restrict__ kmat,
                 const float* __restrict__ v, const int* __restrict__ maski,
                 float* __restrict__ attn, float* __restrict__ outp)
{
    __shared__ __align__(16) uint32_t Ksm[TN * KW];   // bf16 K tile, 18 KB

    const int tid  = threadIdx.x;
    const int warp = tid >> 5;
    const int lane = tid & 31;
    const int g    = lane >> 2;
    const int tig  = lane & 3;
    const int b       = blockIdx.y;
    const int rowBase = blockIdx.x * TM;
    const int r0 = rowBase + warp * 16 + g;
    const int r1 = r0 + 8;

    uint32_t sKsm;
    asm("{ .reg .u64 t; cvta.to.shared.u64 t, %1; cvt.u32.u64 %0, t; }"
        : "=r"(sKsm) : "l"(Ksm));
    const int lm_m = lane >> 3;
    const int lm_r = lane & 7;
    const uint32_t lmBase = sKsm + 4u * ((uint32_t)(8 * (lm_m >> 1) + lm_r) * KW
                                         + (uint32_t)(lm_m & 1) * 4u);

    // ---- A fragments (Q rows r0,r1 as bf16), loaded once ----
    uint32_t aF[4][4];
    {
        const float* q0 = q + ((size_t)b * NN + r0) * DD;
        const float* q1 = q + ((size_t)b * NN + r1) * DD;
        #pragma unroll
        for (int s = 0; s < 4; ++s) {
            float2 x0 = *reinterpret_cast<const float2*>(q0 + 16 * s + 2 * tig);
            float2 x1 = *reinterpret_cast<const float2*>(q1 + 16 * s + 2 * tig);
            float2 x2 = *reinterpret_cast<const float2*>(q0 + 16 * s + 2 * tig + 8);
            float2 x3 = *reinterpret_cast<const float2*>(q1 + 16 * s + 2 * tig + 8);
            aF[s][0] = packbf(x0.x, x0.y);
            aF[s][1] = packbf(x1.x, x1.y);
            aF[s][2] = packbf(x2.x, x2.y);
            aF[s][3] = packbf(x3.x, x3.y);
        }
    }

    const float NEGINF = __int_as_float(NEGINF_BITS);
    float p0[4] = {NEGINF, NEGINF, NEGINF, NEGINF};
    float p1[4] = {NEGINF, NEGINF, NEGINF, NEGINF};

    const int* mr0 = maski + ((size_t)b * NN + r0) * NN + 2 * tig;
    const int* mr1 = maski + ((size_t)b * NN + r1) * NN + 2 * tig;

    // coalesced zero-store base: warp w zeroes rows rowBase + w + 8i
    float* zbase = attn + ((size_t)b * NN + rowBase + warp) * NN + 4 * lane;

    for (int t = 0; t < NT; ++t) {
        if (t) __syncthreads();

        // ---- L2 prefetch of next tile's mask slices (4 lines per row) ----
        if (t + 1 < NT) {
            const char* pa = reinterpret_cast<const char*>(mr0 - 2 * tig + (t + 1) * TN) + tig * 128;
            const char* pb = reinterpret_cast<const char*>(mr1 - 2 * tig + (t + 1) * TN) + tig * 128;
            asm volatile("prefetch.global.L2 [%0];" :: "l"(pa));
            asm volatile("prefetch.global.L2 [%0];" :: "l"(pb));
        }

        // ---- K tile: load + pack + STS in low-register chunks ----
        {
            const float4* src = reinterpret_cast<const float4*>(
                kmat + ((size_t)b * NN + t * TN + (tid >> 1)) * DD) + (tid & 1) * 8;
            uint32_t* dst = Ksm + (tid >> 1) * KW + (tid & 1) * 16;
            #pragma unroll
            for (int h = 0; h < 4; ++h) {
                float4 x = src[2 * h], y = src[2 * h + 1];
                *reinterpret_cast<uint4*>(dst + h * 4) =
                    make_uint4(packbf(x.x, x.y), packbf(x.z, x.w),
                               packbf(y.x, y.y), packbf(y.z, y.w));
            }
        }
        __syncthreads();

        float A0 = NEGINF, B0 = NEGINF, A1 = NEGINF, B1 = NEGINF;
        const int colBase = t * TN;

        #pragma unroll
        for (int jp = 0; jp < 8; ++jp) {     // 16 cols per step
            // mask loads issued first; consumed after LDSM+HMMA below
            const int mo = colBase + 16 * jp;
            int2 mA0 = __ldcs(reinterpret_cast<const int2*>(mr0 + mo));
            int2 mA1 = __ldcs(reinterpret_cast<const int2*>(mr0 + mo + 8));
            int2 mB0 = __ldcs(reinterpret_cast<const int2*>(mr1 + mo));
            int2 mB1 = __ldcs(reinterpret_cast<const int2*>(mr1 + mo + 8));

            float c2[2][4];
            #pragma unroll
            for (int u = 0; u < 2; ++u)
                #pragma unroll
                for (int e = 0; e < 4; ++e) c2[u][e] = 0.f;

            const uint32_t aj = lmBase + 4u * (uint32_t)((16 * jp) * KW);
            #pragma unroll
            for (int s = 0; s < 4; ++s) {
                uint32_t f0, f1, f2, f3;
                ldsm_x4(f0, f1, f2, f3, aj + 32u * s);
                mma16816(c2[0], aF[s], f0, f1);
                mma16816(c2[1], aF[s], f2, f3);
            }

            const int col0 = colBase + 16 * jp + 2 * tig;
            ins2(A0, B0, c2[0][0], (unsigned)mA0.x, col0);
            ins2(A0, B0, c2[0][1], (unsigned)mA0.y, col0 + 1);
            ins2(A1, B1, c2[0][2], (unsigned)mB0.x, col0);
            ins2(A1, B1, c2[0][3], (unsigned)mB0.y, col0 + 1);
            ins2(A0, B0, c2[1][0], (unsigned)mA1.x, col0 + 8);
            ins2(A0, B0, c2[1][1], (unsigned)mA1.y, col0 + 9);
            ins2(A1, B1, c2[1][2], (unsigned)mB1.x, col0 + 8);
            ins2(A1, B1, c2[1][3], (unsigned)mB1.y, col0 + 9);
        }

        ins4(p0, A0); ins4(p0, B0);
        ins4(p1, A1); ins4(p1, B1);

        // ---- coalesced attn zeroing: warp w -> rows w+8i, this tile's cols ----
        {
            float4* zp = reinterpret_cast<float4*>(zbase + t * TN);
            const float4 z = make_float4(0.f, 0.f, 0.f, 0.f);
            #pragma unroll
            for (int i = 0; i < 16; ++i)
                __stcs(zp + (size_t)(8 * i) * (NN / 4), z);
        }
    }

    __syncthreads();   // zeros (block-wide) visible before the 1.0 scatter

    // ---- exact fp32 rescore of <=4 candidates/lane (round-2-verified order) ----
    auto finish = [&](float (&P)[4], int row) {
        float bE = -__int_as_float(0x7f800000);
        int   bI = 0x7fffffff;
        #pragma unroll
        for (int i = 0; i < 4; ++i) {
            if (P[i] != NEGINF) {
                const int cI = __float_as_int(P[i]) & 0x7FF;
                const float4* qr = reinterpret_cast<const float4*>(q + ((size_t)b * NN + row) * DD);
                const float4* kr = reinterpret_cast<const float4*>(kmat + ((size_t)b * NN + cI) * DD);
                float acc = 0.f;
                #pragma unroll
                for (int j2 = 0; j2 < 16; ++j2) {
                    float4 qa = qr[j2], ka = kr[j2];
                    acc = fmaf(qa.x, ka.x, acc);
                    acc = fmaf(qa.y, ka.y, acc);
                    acc = fmaf(qa.z, ka.z, acc);
                    acc = fmaf(qa.w, ka.w, acc);
                }
                if (acc > bE || (acc == bE && cI < bI)) { bE = acc; bI = cI; }
            }
        }
        #pragma unroll
        for (int off = 1; off < 4; off <<= 1) {
            float oE = __shfl_xor_sync(0xffffffffu, bE, off);
            int   oI = __shfl_xor_sync(0xffffffffu, bI, off);
            if (oE > bE || (oE == bE && oI < bI)) { bE = oE; bI = oI; }
        }
        if (bI == 0x7fffffff) bI = 0;
        if (tig == 0) attn[((size_t)b * NN + row) * NN + bI] = 1.0f;
        const float4* vs = reinterpret_cast<const float4*>(v + ((size_t)b * NN + bI) * DD);
        float4* dst = reinterpret_cast<float4*>(outp + ((size_t)b * NN + row) * DD);
        #pragma unroll
        for (int j2 = 0; j2 < 4; ++j2) dst[tig * 4 + j2] = vs[tig * 4 + j2];
    };
    finish(p0, r0);
    finish(p1, r1);
}

extern "C" void kernel_launch(void* const* d_in, const int* in_sizes, int n_in,
                              void* d_out, int out_size) {
    const float* q    = (const float*)d_in[0];
    const float* k    = (const float*)d_in[1];
    const float* v    = (const float*)d_in[2];
    const int*   mask = (const int*)d_in[3];

    float* attn = (float*)d_out;                   // [B, N, N]
    float* outp = attn + (size_t)BB * NN * NN;     // [B, N, D]

    dim3 grid(NN / TM, BB);
    attn_main_kernel<<<grid, THREADS>>>(q, k, v, mask, attn, outp);
}